// round 7
// baseline (speedup 1.0000x reference)
#include <cuda_runtime.h>
#include <cuda_bf16.h>
#include <math.h>
#include <stdint.h>

#define N_NODES 8192
#define KSEL 32
#define ROWS_PER_CTA 32
#define CAP 224
#define COMPACT_HI 96
#define COMPACT_LO 48

__device__ float g_Af[N_NODES * 128];                 // [v1 | -v2] fp32
__device__ float g_Bf[N_NODES * 128];                 // [v2 |  v1] fp32
__device__ __nv_bfloat16 g_Abf[N_NODES * 384];        // [Ahi | Alo | Ahi]
__device__ __nv_bfloat16 g_Bbf[N_NODES * 384];        // [Bhi | Bhi | Blo]

__device__ __forceinline__ uint32_t smem_u32(const void* p) {
    uint32_t a;
    asm("{ .reg .u64 t; cvta.to.shared.u64 t, %1; cvt.u32.u64 %0, t; }" : "=r"(a) : "l"(p));
    return a;
}
__device__ __forceinline__ uint32_t sw128(uint32_t byte) {
    return byte ^ ((byte >> 3) & 0x70);
}
__device__ __forceinline__ void ldmatrix_x4(uint32_t& r0, uint32_t& r1,
                                            uint32_t& r2, uint32_t& r3, uint32_t addr) {
    asm volatile("ldmatrix.sync.aligned.m8n8.x4.shared.b16 {%0,%1,%2,%3}, [%4];"
                 : "=r"(r0), "=r"(r1), "=r"(r2), "=r"(r3) : "r"(addr));
}
__device__ __forceinline__ void mma_bf16(float* c, const uint32_t* a, uint32_t b0, uint32_t b1) {
    asm volatile("mma.sync.aligned.m16n8k16.row.col.f32.bf16.bf16.f32 "
                 "{%0,%1,%2,%3}, {%4,%5,%6,%7}, {%8,%9}, {%0,%1,%2,%3};"
                 : "+f"(c[0]), "+f"(c[1]), "+f"(c[2]), "+f"(c[3])
                 : "r"(a[0]), "r"(a[1]), "r"(a[2]), "r"(a[3]), "r"(b0), "r"(b1));
}
__device__ __forceinline__ void cp_async16(uint32_t dst, const void* src) {
    asm volatile("cp.async.cg.shared.global [%0], [%1], 16;" :: "r"(dst), "l"(src) : "memory");
}
__device__ __forceinline__ void cp_commit() {
    asm volatile("cp.async.commit_group;" ::: "memory");
}
#define CP_WAIT(N) asm volatile("cp.async.wait_group %0;" :: "n"(N) : "memory")

// ---------------------------------------------------------------------------
// Kernel 1: prep (unchanged)
// ---------------------------------------------------------------------------
__global__ void __launch_bounds__(128) prep_kernel(
    const float* __restrict__ emb,
    const float* __restrict__ W1, const float* __restrict__ b1,
    const float* __restrict__ W2, const float* __restrict__ b2)
{
    __shared__ float sW[2][64][65];
    __shared__ float sb[2][64];
    __shared__ float semb[16][64];

    const int tid = threadIdx.x;
    for (int i = tid; i < 64 * 64; i += 128) {
        int r = i >> 6, k = i & 63;
        sW[0][r][k] = W1[i];
        sW[1][r][k] = W2[i];
    }
    if (tid < 64) { sb[0][tid] = b1[tid]; sb[1][tid] = b2[tid]; }

    const int nodeBase = blockIdx.x * 16;
    for (int i = tid; i < 16 * 64; i += 128)
        semb[i >> 6][i & 63] = emb[(size_t)(nodeBase + (i >> 6)) * 64 + (i & 63)];
    __syncthreads();

    const int h = tid >> 6;
    const int r = tid & 63;
    for (int n = 0; n < 16; n++) {
        float acc = sb[h][r];
#pragma unroll
        for (int k = 0; k < 64; k++)
            acc = fmaf(semb[n][k], sW[h][r][k], acc);
        float v = 0.5f * acc * (1.0f + erff(acc * 0.70710678118654752f));
        const int node = nodeBase + n;

        if (h == 0) {
            g_Af[node * 128 + r]      = v;
            g_Bf[node * 128 + 64 + r] = v;
            __nv_bfloat16 hi = __float2bfloat16_rn(v);
            __nv_bfloat16 lo = __float2bfloat16_rn(v - __bfloat162float(hi));
            g_Abf[node * 384 + r]        = hi;
            g_Abf[node * 384 + 128 + r]  = lo;
            g_Abf[node * 384 + 256 + r]  = hi;
            g_Bbf[node * 384 + 64 + r]       = hi;
            g_Bbf[node * 384 + 128 + 64 + r] = hi;
            g_Bbf[node * 384 + 256 + 64 + r] = lo;
        } else {
            float av = -v;
            g_Af[node * 128 + 64 + r] = av;
            g_Bf[node * 128 + r]      = v;
            __nv_bfloat16 ahi = __float2bfloat16_rn(av);
            __nv_bfloat16 alo = __float2bfloat16_rn(av - __bfloat162float(ahi));
            g_Abf[node * 384 + 64 + r]       = ahi;
            g_Abf[node * 384 + 128 + 64 + r] = alo;
            g_Abf[node * 384 + 256 + 64 + r] = ahi;
            __nv_bfloat16 bhi = __float2bfloat16_rn(v);
            __nv_bfloat16 blo = __float2bfloat16_rn(v - __bfloat162float(bhi));
            g_Bbf[node * 384 + r]       = bhi;
            g_Bbf[node * 384 + 128 + r] = bhi;
            g_Bbf[node * 384 + 256 + r] = blo;
        }
    }
}

// ---------------------------------------------------------------------------
// Fused kernel: 256 CTAs x 512 threads, 32-row strips, 256-col tiles
// R5 selection semantics; noise prefetched to smem; cp.async B staging
// ---------------------------------------------------------------------------
#define OFF_A    0            // 6 chunks x 4KB = 24KB
#define OFF_B0   24576        // 32KB
#define OFF_B1   57344        // 32KB
#define OFF_NZ0  90112        // 32 rows x 1040B = 33280 (pad to 34816)
#define OFF_NZ1  124928
#define OFF_CAND 159744       // 32 * 224 * 8 = 57344
#define OFF_THR  217088       // 32 * 4
#define OFF_CNT  217216       // 32 * 4
#define SMEM_FUSED 217600
#define NZ_STRIDE 1040

__global__ void __launch_bounds__(512) fused_kernel(
    const float* __restrict__ noise, float* __restrict__ out)
{
    extern __shared__ char smem[];
    const uint32_t sbase = smem_u32(smem);
    float2* cand = (float2*)(smem + OFF_CAND);
    float*  thr  = (float*)(smem + OFF_THR);
    int*    cnt  = (int*)(smem + OFF_CNT);

    const int tid = threadIdx.x;
    const int lane = tid & 31;
    const int warp = tid >> 5;           // 0..15
    const int warpN = warp & 7;          // 32-col slice
    const int warpM = warp >> 3;         // 16-row slice
    const int rowBase = blockIdx.x * ROWS_PER_CTA;

    // zero output slab
    {
        float4* o4 = (float4*)(out + (size_t)rowBase * N_NODES);
        const float4 z = make_float4(0.f, 0.f, 0.f, 0.f);
        for (int i = tid; i < ROWS_PER_CTA * N_NODES / 4; i += 512) o4[i] = z;
    }
    if (tid < 32) { thr[tid] = -1.0f; cnt[tid] = 0; }

    // load A strip: 32 rows x 768B, 6 chunks of 4KB, SW128
    {
        const char* gA = (const char*)g_Abf;
        for (int idx = tid; idx < 1536; idx += 512) {
            int row = idx / 48, rem = idx % 48;
            int c = rem >> 3, q = rem & 7;
            uint4 v = *(const uint4*)(gA + (size_t)(rowBase + row) * 768 + c * 128 + q * 16);
            *(uint4*)(smem + OFF_A + c * 4096 + sw128(row * 128 + q * 16)) = v;
        }
    }

    const int laneRow = lane & 15;
    const int laneK = lane >> 4;
    const int rowB = tid >> 3;           // 0..63
    const int qB = tid & 7;
    uint32_t stB[4];
#pragma unroll
    for (int r = 0; r < 4; r++)
        stB[r] = sw128((rowB + r * 64) * 128 + qB * 16);

    const char* gB = (const char*)g_Bbf;
    const int lr0 = warpM * 16 + (lane >> 2);

    auto issueB = [&](int g) {
        const uint32_t dstBase = sbase + ((g & 1) ? OFF_B1 : OFF_B0);
        const int tt = g / 6, cc = g - tt * 6;
        const char* src = gB + (size_t)(tt * 256 + rowB) * 768 + cc * 128 + qB * 16;
#pragma unroll
        for (int r = 0; r < 4; r++)
            cp_async16(dstBase + stB[r], src + (size_t)r * 64 * 768);
        cp_commit();
    };
    auto issueNZ = [&](int tt) {
        const uint32_t dstBase = sbase + ((tt & 1) ? OFF_NZ1 : OFF_NZ0);
#pragma unroll
        for (int k = 0; k < 4; k++) {
            int u = tid + k * 512;
            int nr = u >> 6, seg = u & 63;
            cp_async16(dstBase + nr * NZ_STRIDE + seg * 16,
                       noise + (size_t)(rowBase + nr) * N_NODES + tt * 256 + seg * 4);
        }
        cp_commit();
    };

    // prologue: commit order [B(0,0), NZ(0)]
    issueB(0);
    issueNZ(0);

    for (int t = 0; t < 32; t++) {
        const int colBase = t * 256;

        float acc[4][4];
#pragma unroll
        for (int n8 = 0; n8 < 4; n8++)
#pragma unroll
            for (int q = 0; q < 4; q++) acc[n8][q] = 0.0f;

        for (int c = 0; c < 6; c++) {
            const int g = t * 6 + c;
            if (c == 0) { CP_WAIT(1); } else { CP_WAIT(0); }
            __syncthreads();

            const uint32_t aBuf = sbase + OFF_A + c * 4096;
            const uint32_t bBuf = sbase + ((c & 1) ? OFF_B1 : OFF_B0);
#pragma unroll
            for (int ks = 0; ks < 4; ks++) {
                uint32_t afr[4];
                ldmatrix_x4(afr[0], afr[1], afr[2], afr[3],
                            aBuf + sw128((warpM * 16 + laneRow) * 128 + ks * 32 + laneK * 16));
#pragma unroll
                for (int nq = 0; nq < 2; nq++) {
                    uint32_t r0, r1, r2, r3;
                    ldmatrix_x4(r0, r1, r2, r3,
                                bBuf + sw128((warpN * 32 + nq * 16 + laneRow) * 128 + ks * 32 + laneK * 16));
                    mma_bf16(acc[nq * 2],     afr, r0, r2);
                    mma_bf16(acc[nq * 2 + 1], afr, r1, r3);
                }
            }
            if (g < 191) {
                issueB(g + 1);
                if (c == 5) issueNZ(t + 1);   // commit order [B(t+1,0), NZ(t+1)]
            }
        }

        // ---- append: scores (R5 semantics, noise from smem), two phases ----
        const char* nzBuf = smem + ((t & 1) ? OFF_NZ1 : OFF_NZ0);
#pragma unroll 1
        for (int ph = 0; ph < 2; ph++) {
            if ((warpN >> 2) == ph) {
                const float th0 = thr[lr0];
                const float th1 = thr[lr0 + 8];
#pragma unroll
                for (int n8 = 0; n8 < 4; n8++) {
                    const int cl = warpN * 32 + n8 * 8 + (lane & 3) * 2;
                    const int col = colBase + cl;
                    float2 nz0 = *(const float2*)(nzBuf + lr0 * NZ_STRIDE + cl * 4);
                    float s0 = fmaxf(acc[n8][0], 0.f) + 0.01f * nz0.x;
                    float s1 = fmaxf(acc[n8][1], 0.f) + 0.01f * nz0.y;
                    if (s0 > th0) {
                        int p = atomicAdd(&cnt[lr0], 1);
                        if (p < CAP) cand[lr0 * CAP + p] = make_float2(s0, __int_as_float(col));
                    }
                    if (s1 > th0) {
                        int p = atomicAdd(&cnt[lr0], 1);
                        if (p < CAP) cand[lr0 * CAP + p] = make_float2(s1, __int_as_float(col + 1));
                    }
                    float2 nz1 = *(const float2*)(nzBuf + (lr0 + 8) * NZ_STRIDE + cl * 4);
                    float s2 = fmaxf(acc[n8][2], 0.f) + 0.01f * nz1.x;
                    float s3 = fmaxf(acc[n8][3], 0.f) + 0.01f * nz1.y;
                    if (s2 > th1) {
                        int p = atomicAdd(&cnt[lr0 + 8], 1);
                        if (p < CAP) cand[(lr0 + 8) * CAP + p] = make_float2(s2, __int_as_float(col));
                    }
                    if (s3 > th1) {
                        int p = atomicAdd(&cnt[lr0 + 8], 1);
                        if (p < CAP) cand[(lr0 + 8) * CAP + p] = make_float2(s3, __int_as_float(col + 1));
                    }
                }
            }
            __syncthreads();

            // ---- compaction: warp w owns rows w*2, w*2+1 ----
#pragma unroll 1
            for (int rr = 0; rr < 2; rr++) {
                const int r = warp * 2 + rr;
                int n = cnt[r];
                if (n > COMPACT_HI) {
                    if (n > CAP) n = CAP;
                    unsigned sbits[7];
#pragma unroll
                    for (int q = 0; q < 7; q++) {
                        int i = lane + q * 32;
                        sbits[q] = (i < n) ? __float_as_uint(cand[r * CAP + i].x) : 0u;
                    }
                    unsigned lo = 0, hi = 0x7f800000u, T = 0;
                    for (int it = 0; it < 32; it++) {
                        unsigned mid = lo + ((hi - lo) >> 1);
                        int c = 0;
#pragma unroll
                        for (int q = 0; q < 7; q++)
                            c += __popc(__ballot_sync(0xffffffffu, sbits[q] > mid));
                        if (c > COMPACT_HI) lo = mid + 1;
                        else if (c < COMPACT_LO) { if (mid == 0) { T = 0; break; } hi = mid - 1; }
                        else { T = mid; break; }
                        if (lo > hi) { T = hi; break; }
                    }
                    int base = 0;
#pragma unroll
                    for (int q = 0; q < 7; q++) {
                        int i = lane + q * 32;
                        bool keep = (i < n) && (sbits[q] > T);
                        unsigned m = __ballot_sync(0xffffffffu, keep);
                        float2 v;
                        if (keep) v = cand[r * CAP + i];
                        int pos = base + __popc(m & ((1u << lane) - 1u));
                        if (keep) cand[r * CAP + pos] = v;
                        base += __popc(m);
                    }
                    if (lane == 0) { cnt[r] = base; thr[r] = __uint_as_float(T); }
                }
                __syncwarp();
            }
            __syncthreads();
        }
    }

    // ------ tail: exact rescore + exact top-32 per row ------
    {
        float4* saf4 = (float4*)(smem + OFF_B0);   // 32 rows x 128 fp32 = 16KB
        for (int idx = tid; idx < 32 * 32; idx += 512) {
            int row = idx >> 5, k4 = idx & 31;
            saf4[idx] = *(const float4*)(g_Af + (size_t)(rowBase + row) * 128 + k4 * 4);
        }
    }
    __syncthreads();

    const float4* saf = (const float4*)(smem + OFF_B0);
    int* win = (int*)(smem + OFF_A) + warp * 64;

#pragma unroll 1
    for (int rr = 0; rr < 2; rr++) {
        const int r = warp * 2 + rr;
        const int rowG = rowBase + r;
        int n = cnt[r];
        if (n > CAP) n = CAP;

        for (int i = lane; i < n; i += 32) {
            const int j = __float_as_int(cand[r * CAP + i].y);
            float d = 0.f;
#pragma unroll
            for (int k4 = 0; k4 < 32; k4++) {
                float4 a = saf[r * 32 + k4];
                float4 b = *(const float4*)(g_Bf + (size_t)j * 128 + k4 * 4);
                d = fmaf(a.x, b.x, fmaf(a.y, b.y, fmaf(a.z, b.z, fmaf(a.w, b.w, d))));
            }
            float adjv = fmaxf(d, 0.f);
            float sc = __fadd_rn(adjv, __fmul_rn(0.01f, __ldg(noise + (size_t)rowG * N_NODES + j)));
            cand[r * CAP + i].x = sc;
        }
        __syncwarp();

        unsigned sbits[7];
#pragma unroll
        for (int q = 0; q < 7; q++) {
            int i = lane + q * 32;
            sbits[q] = (i < n) ? __float_as_uint(cand[r * CAP + i].x) : 0u;
        }
        unsigned lo = 0, hi = 0x7f800000u, T = 0;
        for (int it = 0; it < 32; it++) {
            unsigned mid = lo + ((hi - lo) >> 1);
            int c = 0;
#pragma unroll
            for (int q = 0; q < 7; q++)
                c += __popc(__ballot_sync(0xffffffffu, sbits[q] > mid));
            if (c > 48) lo = mid + 1;
            else if (c < 32) { if (mid == 0) { T = 0; break; } hi = mid - 1; }
            else { T = mid; break; }
            if (lo > hi) { T = hi; break; }
        }

        int wn = 0;
#pragma unroll
        for (int q = 0; q < 7; q++) {
            int i = lane + q * 32;
            bool keep = (i < n) && (sbits[q] > T);
            unsigned m = __ballot_sync(0xffffffffu, keep);
            int pos = wn + __popc(m & ((1u << lane) - 1u));
            if (keep && pos < 64) win[pos] = i;
            wn += __popc(m);
        }
        if (wn > 64) wn = 64;
        __syncwarp();

        while (wn > KSEL) {
            unsigned long long bk = ~0ull; int bp = -1;
            for (int p = lane; p < wn; p += 32) {
                float2 e = cand[r * CAP + win[p]];
                unsigned long long key =
                    ((unsigned long long)__float_as_uint(e.x) << 32)
                  | (unsigned)(0xFFFFFFFFu - (unsigned)__float_as_int(e.y));
                if (key < bk) { bk = key; bp = p; }
            }
#pragma unroll
            for (int off = 16; off > 0; off >>= 1) {
                unsigned long long ok = __shfl_down_sync(0xffffffffu, bk, off);
                int op = __shfl_down_sync(0xffffffffu, bp, off);
                if (ok < bk) { bk = ok; bp = op; }
            }
            bp = __shfl_sync(0xffffffffu, bp, 0);
            if (lane == 0) win[bp] = win[wn - 1];
            __syncwarp();
            wn--;
        }

        if (lane < wn) {
            const int j = __float_as_int(cand[r * CAP + win[lane]].y);
            float d = 0.f;
#pragma unroll
            for (int k4 = 0; k4 < 32; k4++) {
                float4 a = saf[r * 32 + k4];
                float4 b = *(const float4*)(g_Bf + (size_t)j * 128 + k4 * 4);
                d = fmaf(a.x, b.x, fmaf(a.y, b.y, fmaf(a.z, b.z, fmaf(a.w, b.w, d))));
            }
            out[(size_t)rowG * N_NODES + j] = fmaxf(d, 0.f);
        }
        __syncwarp();
    }
}

// ---------------------------------------------------------------------------
extern "C" void kernel_launch(void* const* d_in, const int* in_sizes, int n_in,
                              void* d_out, int out_size)
{
    const float* emb   = (const float*)d_in[0];
    const float* noise = (const float*)d_in[1];
    const float* W1    = (const float*)d_in[2];
    const float* b1    = (const float*)d_in[3];
    const float* W2    = (const float*)d_in[4];
    const float* b2    = (const float*)d_in[5];
    float* out = (float*)d_out;

    cudaFuncSetAttribute(fused_kernel, cudaFuncAttributeMaxDynamicSharedMemorySize, SMEM_FUSED);

    prep_kernel<<<N_NODES / 16, 128>>>(emb, W1, b1, W2, b2);
    fused_kernel<<<N_NODES / ROWS_PER_CTA, 512, SMEM_FUSED>>>(noise, out);
}

// round 8
// speedup vs baseline: 1.2685x; 1.2685x over previous
#include <cuda_runtime.h>
#include <cuda_bf16.h>
#include <math.h>
#include <stdint.h>

#define N_NODES 8192
#define KSEL 32
#define ROWS_PER_CTA 64
#define CAP 256
#define COMPACT_HI 128   // compact only when count exceeds this (prevents re-trigger churn)

__device__ float g_Af[N_NODES * 128];                 // [v1 | -v2] fp32
__device__ float g_Bf[N_NODES * 128];                 // [v2 |  v1] fp32
__device__ __nv_bfloat16 g_Abf[N_NODES * 384];        // [Ahi | Alo | Ahi]
__device__ __nv_bfloat16 g_Bbf[N_NODES * 384];        // [Bhi | Bhi | Blo]

__device__ __forceinline__ uint32_t smem_u32(const void* p) {
    uint32_t a;
    asm("{ .reg .u64 t; cvta.to.shared.u64 t, %1; cvt.u32.u64 %0, t; }" : "=r"(a) : "l"(p));
    return a;
}
__device__ __forceinline__ uint32_t sw128(uint32_t byte) {
    return byte ^ ((byte >> 3) & 0x70);
}
__device__ __forceinline__ void ldmatrix_x4(uint32_t& r0, uint32_t& r1,
                                            uint32_t& r2, uint32_t& r3, uint32_t addr) {
    asm volatile("ldmatrix.sync.aligned.m8n8.x4.shared.b16 {%0,%1,%2,%3}, [%4];"
                 : "=r"(r0), "=r"(r1), "=r"(r2), "=r"(r3) : "r"(addr));
}
__device__ __forceinline__ void mma_bf16(float* c, const uint32_t* a, uint32_t b0, uint32_t b1) {
    asm volatile("mma.sync.aligned.m16n8k16.row.col.f32.bf16.bf16.f32 "
                 "{%0,%1,%2,%3}, {%4,%5,%6,%7}, {%8,%9}, {%0,%1,%2,%3};"
                 : "+f"(c[0]), "+f"(c[1]), "+f"(c[2]), "+f"(c[3])
                 : "r"(a[0]), "r"(a[1]), "r"(a[2]), "r"(a[3]), "r"(b0), "r"(b1));
}
__device__ __forceinline__ void cp_async16(uint32_t dst, const void* src) {
    asm volatile("cp.async.cg.shared.global [%0], [%1], 16;" :: "r"(dst), "l"(src) : "memory");
}
__device__ __forceinline__ void cp_commit() {
    asm volatile("cp.async.commit_group;" ::: "memory");
}
#define CP_WAIT(N) asm volatile("cp.async.wait_group %0;" :: "n"(N) : "memory")

// ---------------------------------------------------------------------------
// Kernel 1: prep (unchanged)
// ---------------------------------------------------------------------------
__global__ void __launch_bounds__(128) prep_kernel(
    const float* __restrict__ emb,
    const float* __restrict__ W1, const float* __restrict__ b1,
    const float* __restrict__ W2, const float* __restrict__ b2)
{
    __shared__ float sW[2][64][65];
    __shared__ float sb[2][64];
    __shared__ float semb[16][64];

    const int tid = threadIdx.x;
    for (int i = tid; i < 64 * 64; i += 128) {
        int r = i >> 6, k = i & 63;
        sW[0][r][k] = W1[i];
        sW[1][r][k] = W2[i];
    }
    if (tid < 64) { sb[0][tid] = b1[tid]; sb[1][tid] = b2[tid]; }

    const int nodeBase = blockIdx.x * 16;
    for (int i = tid; i < 16 * 64; i += 128)
        semb[i >> 6][i & 63] = emb[(size_t)(nodeBase + (i >> 6)) * 64 + (i & 63)];
    __syncthreads();

    const int h = tid >> 6;
    const int r = tid & 63;
    for (int n = 0; n < 16; n++) {
        float acc = sb[h][r];
#pragma unroll
        for (int k = 0; k < 64; k++)
            acc = fmaf(semb[n][k], sW[h][r][k], acc);
        float v = 0.5f * acc * (1.0f + erff(acc * 0.70710678118654752f));
        const int node = nodeBase + n;

        if (h == 0) {
            g_Af[node * 128 + r]      = v;
            g_Bf[node * 128 + 64 + r] = v;
            __nv_bfloat16 hi = __float2bfloat16_rn(v);
            __nv_bfloat16 lo = __float2bfloat16_rn(v - __bfloat162float(hi));
            g_Abf[node * 384 + r]        = hi;
            g_Abf[node * 384 + 128 + r]  = lo;
            g_Abf[node * 384 + 256 + r]  = hi;
            g_Bbf[node * 384 + 64 + r]       = hi;
            g_Bbf[node * 384 + 128 + 64 + r] = hi;
            g_Bbf[node * 384 + 256 + 64 + r] = lo;
        } else {
            float av = -v;
            g_Af[node * 128 + 64 + r] = av;
            g_Bf[node * 128 + r]      = v;
            __nv_bfloat16 ahi = __float2bfloat16_rn(av);
            __nv_bfloat16 alo = __float2bfloat16_rn(av - __bfloat162float(ahi));
            g_Abf[node * 384 + 64 + r]       = ahi;
            g_Abf[node * 384 + 128 + 64 + r] = alo;
            g_Abf[node * 384 + 256 + 64 + r] = ahi;
            __nv_bfloat16 bhi = __float2bfloat16_rn(v);
            __nv_bfloat16 blo = __float2bfloat16_rn(v - __bfloat162float(bhi));
            g_Bbf[node * 384 + r]       = bhi;
            g_Bbf[node * 384 + 128 + r] = bhi;
            g_Bbf[node * 384 + 256 + r] = blo;
        }
    }
}

// ---------------------------------------------------------------------------
// Fused kernel: 128 CTAs x 512 threads, 64-row strips, 256-col tiles.
// Adj-only filter (zero-clamped margin); noise touched ONLY in the tail.
// ---------------------------------------------------------------------------
#define OFF_A    0            // 6 chunks x 8KB = 48KB
#define OFF_B0   49152        // 32KB
#define OFF_B1   81920        // 32KB
#define OFF_CS   114688       // 64 * 256 * 4 = 65536 (candidate adj values)
#define OFF_CJ   180224       // 64 * 256 * 2 = 32768 (candidate cols, u16)
#define OFF_THR  212992       // 64 * 4
#define OFF_CNT  213248       // 64 * 4
#define SMEM_FUSED 213504

__global__ void __launch_bounds__(512) fused_kernel(
    const float* __restrict__ noise, float* __restrict__ out)
{
    extern __shared__ char smem[];
    const uint32_t sbase = smem_u32(smem);
    float*    cs  = (float*)(smem + OFF_CS);
    uint16_t* cj  = (uint16_t*)(smem + OFF_CJ);
    float*    thr = (float*)(smem + OFF_THR);
    int*      cnt = (int*)(smem + OFF_CNT);

    const int tid = threadIdx.x;
    const int lane = tid & 31;
    const int warp = tid >> 5;           // 0..15
    const int warpN = warp & 7;          // 32-col slice
    const int warpM = warp >> 3;         // 32-row slice
    const int rowBase = blockIdx.x * ROWS_PER_CTA;

    // zero output slab
    {
        float4* o4 = (float4*)(out + (size_t)rowBase * N_NODES);
        const float4 z = make_float4(0.f, 0.f, 0.f, 0.f);
        for (int i = tid; i < ROWS_PER_CTA * N_NODES / 4; i += 512) o4[i] = z;
    }
    if (tid < 64) { thr[tid] = -1.0f; cnt[tid] = 0; }

    // load A strip: 64 rows x 768B, 6 chunks of 8KB, SW128
    {
        const char* gA = (const char*)g_Abf;
        for (int idx = tid; idx < 3072; idx += 512) {
            int row = idx / 48, rem = idx % 48;
            int c = rem >> 3, q = rem & 7;
            uint4 v = *(const uint4*)(gA + (size_t)(rowBase + row) * 768 + c * 128 + q * 16);
            *(uint4*)(smem + OFF_A + c * 8192 + sw128(row * 128 + q * 16)) = v;
        }
    }

    const int laneRow = lane & 15;
    const int laneK = lane >> 4;
    const int rowB = tid >> 3;           // 0..63
    const int qB = tid & 7;
    uint32_t stB[4];
#pragma unroll
    for (int r = 0; r < 4; r++)
        stB[r] = sw128((rowB + r * 64) * 128 + qB * 16);

    const char* gB = (const char*)g_Bbf;
    const int lrBase = warpM * 32 + (lane >> 2);

    auto issueB = [&](int g) {
        const uint32_t dstBase = sbase + ((g & 1) ? OFF_B1 : OFF_B0);
        const int tt = g / 6, cc = g - tt * 6;
        const char* src = gB + (size_t)(tt * 256 + rowB) * 768 + cc * 128 + qB * 16;
#pragma unroll
        for (int r = 0; r < 4; r++)
            cp_async16(dstBase + stB[r], src + (size_t)r * 64 * 768);
        cp_commit();
    };

    issueB(0);

    for (int t = 0; t < 32; t++) {
        const int colBase = t * 256;

        float acc[2][4][4];
#pragma unroll
        for (int mi = 0; mi < 2; mi++)
#pragma unroll
            for (int n8 = 0; n8 < 4; n8++)
#pragma unroll
                for (int q = 0; q < 4; q++) acc[mi][n8][q] = 0.0f;

        for (int c = 0; c < 6; c++) {
            const int g = t * 6 + c;
            CP_WAIT(0);
            __syncthreads();

            const uint32_t aBuf = sbase + OFF_A + c * 8192;
            const uint32_t bBuf = sbase + ((g & 1) ? OFF_B1 : OFF_B0);
#pragma unroll
            for (int ks = 0; ks < 4; ks++) {
                uint32_t afr[2][4];
#pragma unroll
                for (int mi = 0; mi < 2; mi++)
                    ldmatrix_x4(afr[mi][0], afr[mi][1], afr[mi][2], afr[mi][3],
                                aBuf + sw128((warpM * 32 + mi * 16 + laneRow) * 128 + ks * 32 + laneK * 16));
#pragma unroll
                for (int nq = 0; nq < 2; nq++) {
                    uint32_t r0, r1, r2, r3;
                    ldmatrix_x4(r0, r1, r2, r3,
                                bBuf + sw128((warpN * 32 + nq * 16 + laneRow) * 128 + ks * 32 + laneK * 16));
#pragma unroll
                    for (int mi = 0; mi < 2; mi++) {
                        mma_bf16(acc[mi][nq * 2],     afr[mi], r0, r2);
                        mma_bf16(acc[mi][nq * 2 + 1], afr[mi], r1, r3);
                    }
                }
            }
            if (g < 191) issueB(g + 1);
        }

        // ---- append: adj-only (register compare, zero DRAM), two phases ----
#pragma unroll 1
        for (int ph = 0; ph < 2; ph++) {
            if ((warpN >> 2) == ph) {
#pragma unroll
                for (int mi = 0; mi < 2; mi++) {
                    const int lr = lrBase + mi * 16;
                    const float th0 = thr[lr];
                    const float th1 = thr[lr + 8];
#pragma unroll
                    for (int n8 = 0; n8 < 4; n8++) {
                        const int col = colBase + warpN * 32 + n8 * 8 + (lane & 3) * 2;
                        float s0 = fmaxf(acc[mi][n8][0], 0.f);
                        float s1 = fmaxf(acc[mi][n8][1], 0.f);
                        float s2 = fmaxf(acc[mi][n8][2], 0.f);
                        float s3 = fmaxf(acc[mi][n8][3], 0.f);
                        if (s0 > th0) {
                            int p = atomicAdd(&cnt[lr], 1);
                            if (p < CAP) { cs[lr * CAP + p] = s0; cj[lr * CAP + p] = (uint16_t)col; }
                        }
                        if (s1 > th0) {
                            int p = atomicAdd(&cnt[lr], 1);
                            if (p < CAP) { cs[lr * CAP + p] = s1; cj[lr * CAP + p] = (uint16_t)(col + 1); }
                        }
                        if (s2 > th1) {
                            int p = atomicAdd(&cnt[lr + 8], 1);
                            if (p < CAP) { cs[(lr + 8) * CAP + p] = s2; cj[(lr + 8) * CAP + p] = (uint16_t)col; }
                        }
                        if (s3 > th1) {
                            int p = atomicAdd(&cnt[lr + 8], 1);
                            if (p < CAP) { cs[(lr + 8) * CAP + p] = s3; cj[(lr + 8) * CAP + p] = (uint16_t)(col + 1); }
                        }
                    }
                }
            }
            __syncthreads();

            // ---- compaction: warp w owns rows w*4 .. w*4+3 ----
#pragma unroll 1
            for (int rr = 0; rr < 4; rr++) {
                const int r = warp * 4 + rr;
                int n = cnt[r];
                if (n > COMPACT_HI) {
                    if (n > CAP) n = CAP;
                    unsigned sbits[8];
#pragma unroll
                    for (int q = 0; q < 8; q++) {
                        int i = lane + q * 32;
                        sbits[q] = (i < n) ? __float_as_uint(cs[r * CAP + i]) : 0u;
                    }
                    unsigned lo = 0, hi = 0x7f800000u, T = 0;
                    for (int it = 0; it < 32; it++) {
                        unsigned mid = lo + ((hi - lo) >> 1);
                        int c = 0;
#pragma unroll
                        for (int q = 0; q < 8; q++)
                            c += __popc(__ballot_sync(0xffffffffu, sbits[q] > mid));
                        if (c > 96) lo = mid + 1;
                        else if (c < 48) { if (mid == 0) { T = 0; break; } hi = mid - 1; }
                        else { T = mid; break; }
                        if (lo > hi) { T = hi; break; }
                    }
                    // keep adj > max(T - 0.01, eps): 0.01 noise margin, but zeros
                    // (adj == 0) can NEVER be candidates (fixes R6 zero-flood).
                    const float fT = fmaxf(__uint_as_float(T) - 0.01f, 1e-30f);
                    int base = 0;
#pragma unroll
                    for (int q = 0; q < 8; q++) {
                        int i = lane + q * 32;
                        bool keep = (i < n) && (__uint_as_float(sbits[q]) > fT);
                        unsigned m = __ballot_sync(0xffffffffu, keep);
                        float v; uint16_t jv;
                        if (keep) { v = cs[r * CAP + i]; jv = cj[r * CAP + i]; }
                        int pos = base + __popc(m & ((1u << lane) - 1u));
                        if (keep) { cs[r * CAP + pos] = v; cj[r * CAP + pos] = jv; }
                        base += __popc(m);
                    }
                    if (lane == 0) { cnt[r] = base; thr[r] = fT; }
                }
                __syncwarp();
            }
            __syncthreads();
        }
    }

    // ------ tail: exact rescore (fp32 dot + noise) + exact top-32 per row ------
    {
        float4* saf4 = (float4*)(smem + OFF_B0);   // 64 rows x 128 fp32 = 32KB
        for (int idx = tid; idx < 64 * 32; idx += 512) {
            int row = idx >> 5, k4 = idx & 31;
            saf4[idx] = *(const float4*)(g_Af + (size_t)(rowBase + row) * 128 + k4 * 4);
        }
    }
    __syncthreads();

    const float4* saf = (const float4*)(smem + OFF_B0);
    int* win = (int*)(smem + OFF_A) + warp * 64;

#pragma unroll 1
    for (int rr = 0; rr < 4; rr++) {
        const int r = warp * 4 + rr;
        const int rowG = rowBase + r;
        int n = cnt[r];
        if (n > CAP) n = CAP;

        // exact score = relu(fp32 dot) + 0.01*noise, overwrite cs
        for (int i = lane; i < n; i += 32) {
            const int j = (int)cj[r * CAP + i];
            float d = 0.f;
#pragma unroll
            for (int k4 = 0; k4 < 32; k4++) {
                float4 a = saf[r * 32 + k4];
                float4 b = *(const float4*)(g_Bf + (size_t)j * 128 + k4 * 4);
                d = fmaf(a.x, b.x, fmaf(a.y, b.y, fmaf(a.z, b.z, fmaf(a.w, b.w, d))));
            }
            float adjv = fmaxf(d, 0.f);
            float sc = __fadd_rn(adjv, __fmul_rn(0.01f, __ldg(noise + (size_t)rowG * N_NODES + j)));
            cs[r * CAP + i] = sc;
        }
        __syncwarp();

        unsigned sbits[8];
#pragma unroll
        for (int q = 0; q < 8; q++) {
            int i = lane + q * 32;
            sbits[q] = (i < n) ? __float_as_uint(cs[r * CAP + i]) : 0u;
        }
        unsigned lo = 0, hi = 0x7f800000u, T = 0;
        for (int it = 0; it < 32; it++) {
            unsigned mid = lo + ((hi - lo) >> 1);
            int c = 0;
#pragma unroll
            for (int q = 0; q < 8; q++)
                c += __popc(__ballot_sync(0xffffffffu, sbits[q] > mid));
            if (c > 48) lo = mid + 1;
            else if (c < 32) { if (mid == 0) { T = 0; break; } hi = mid - 1; }
            else { T = mid; break; }
            if (lo > hi) { T = hi; break; }
        }

        int wn = 0;
#pragma unroll
        for (int q = 0; q < 8; q++) {
            int i = lane + q * 32;
            bool keep = (i < n) && (sbits[q] > T);
            unsigned m = __ballot_sync(0xffffffffu, keep);
            int pos = wn + __popc(m & ((1u << lane) - 1u));
            if (keep && pos < 64) win[pos] = i;
            wn += __popc(m);
        }
        if (wn > 64) wn = 64;
        __syncwarp();

        while (wn > KSEL) {
            unsigned long long bk = ~0ull; int bp = -1;
            for (int p = lane; p < wn; p += 32) {
                int i = win[p];
                unsigned long long key =
                    ((unsigned long long)__float_as_uint(cs[r * CAP + i]) << 32)
                  | (unsigned)(0xFFFFu - cj[r * CAP + i]);
                if (key < bk) { bk = key; bp = p; }
            }
#pragma unroll
            for (int off = 16; off > 0; off >>= 1) {
                unsigned long long ok = __shfl_down_sync(0xffffffffu, bk, off);
                int op = __shfl_down_sync(0xffffffffu, bp, off);
                if (ok < bk) { bk = ok; bp = op; }
            }
            bp = __shfl_sync(0xffffffffu, bp, 0);
            if (lane == 0) win[bp] = win[wn - 1];
            __syncwarp();
            wn--;
        }

        if (lane < wn) {
            const int j = (int)cj[r * CAP + win[lane]];
            float d = 0.f;
#pragma unroll
            for (int k4 = 0; k4 < 32; k4++) {
                float4 a = saf[r * 32 + k4];
                float4 b = *(const float4*)(g_Bf + (size_t)j * 128 + k4 * 4);
                d = fmaf(a.x, b.x, fmaf(a.y, b.y, fmaf(a.z, b.z, fmaf(a.w, b.w, d))));
            }
            out[(size_t)rowG * N_NODES + j] = fmaxf(d, 0.f);
        }
        __syncwarp();
    }
}

// ---------------------------------------------------------------------------
extern "C" void kernel_launch(void* const* d_in, const int* in_sizes, int n_in,
                              void* d_out, int out_size)
{
    const float* emb   = (const float*)d_in[0];
    const float* noise = (const float*)d_in[1];
    const float* W1    = (const float*)d_in[2];
    const float* b1    = (const float*)d_in[3];
    const float* W2    = (const float*)d_in[4];
    const float* b2    = (const float*)d_in[5];
    float* out = (float*)d_out;

    cudaFuncSetAttribute(fused_kernel, cudaFuncAttributeMaxDynamicSharedMemorySize, SMEM_FUSED);

    prep_kernel<<<N_NODES / 16, 128>>>(emb, W1, b1, W2, b2);
    fused_kernel<<<N_NODES / ROWS_PER_CTA, 512, SMEM_FUSED>>>(noise, out);
}

// round 9
// speedup vs baseline: 1.3021x; 1.0265x over previous
#include <cuda_runtime.h>
#include <cuda_bf16.h>
#include <math.h>
#include <stdint.h>

#define N_NODES 8192
#define KSEL 32
#define ROWS_PER_CTA 64
#define CAP 256
#define COMPACT_HI 128

__device__ float g_Af[N_NODES * 128];                 // [v1 | -v2] fp32
__device__ float g_Bf[N_NODES * 128];                 // [v2 |  v1] fp32
__device__ __nv_bfloat16 g_Abf[N_NODES * 384];        // [Ahi | Alo | Ahi]
__device__ __nv_bfloat16 g_Bbf[N_NODES * 384];        // [Bhi | Bhi | Blo]

__device__ __forceinline__ uint32_t smem_u32(const void* p) {
    uint32_t a;
    asm("{ .reg .u64 t; cvta.to.shared.u64 t, %1; cvt.u32.u64 %0, t; }" : "=r"(a) : "l"(p));
    return a;
}
__device__ __forceinline__ uint32_t sw128(uint32_t byte) {
    return byte ^ ((byte >> 3) & 0x70);
}
__device__ __forceinline__ void ldmatrix_x4(uint32_t& r0, uint32_t& r1,
                                            uint32_t& r2, uint32_t& r3, uint32_t addr) {
    asm volatile("ldmatrix.sync.aligned.m8n8.x4.shared.b16 {%0,%1,%2,%3}, [%4];"
                 : "=r"(r0), "=r"(r1), "=r"(r2), "=r"(r3) : "r"(addr));
}
__device__ __forceinline__ void mma_bf16(float* c, const uint32_t* a, uint32_t b0, uint32_t b1) {
    asm volatile("mma.sync.aligned.m16n8k16.row.col.f32.bf16.bf16.f32 "
                 "{%0,%1,%2,%3}, {%4,%5,%6,%7}, {%8,%9}, {%0,%1,%2,%3};"
                 : "+f"(c[0]), "+f"(c[1]), "+f"(c[2]), "+f"(c[3])
                 : "r"(a[0]), "r"(a[1]), "r"(a[2]), "r"(a[3]), "r"(b0), "r"(b1));
}
__device__ __forceinline__ void cp_async16(uint32_t dst, const void* src) {
    asm volatile("cp.async.cg.shared.global [%0], [%1], 16;" :: "r"(dst), "l"(src) : "memory");
}
__device__ __forceinline__ void cp_commit() {
    asm volatile("cp.async.commit_group;" ::: "memory");
}
#define CP_WAIT(N) asm volatile("cp.async.wait_group %0;" :: "n"(N) : "memory")

// ---------------------------------------------------------------------------
// Kernel 1: prep (unchanged)
// ---------------------------------------------------------------------------
__global__ void __launch_bounds__(128) prep_kernel(
    const float* __restrict__ emb,
    const float* __restrict__ W1, const float* __restrict__ b1,
    const float* __restrict__ W2, const float* __restrict__ b2)
{
    __shared__ float sW[2][64][65];
    __shared__ float sb[2][64];
    __shared__ float semb[16][64];

    const int tid = threadIdx.x;
    for (int i = tid; i < 64 * 64; i += 128) {
        int r = i >> 6, k = i & 63;
        sW[0][r][k] = W1[i];
        sW[1][r][k] = W2[i];
    }
    if (tid < 64) { sb[0][tid] = b1[tid]; sb[1][tid] = b2[tid]; }

    const int nodeBase = blockIdx.x * 16;
    for (int i = tid; i < 16 * 64; i += 128)
        semb[i >> 6][i & 63] = emb[(size_t)(nodeBase + (i >> 6)) * 64 + (i & 63)];
    __syncthreads();

    const int h = tid >> 6;
    const int r = tid & 63;
    for (int n = 0; n < 16; n++) {
        float acc = sb[h][r];
#pragma unroll
        for (int k = 0; k < 64; k++)
            acc = fmaf(semb[n][k], sW[h][r][k], acc);
        float v = 0.5f * acc * (1.0f + erff(acc * 0.70710678118654752f));
        const int node = nodeBase + n;

        if (h == 0) {
            g_Af[node * 128 + r]      = v;
            g_Bf[node * 128 + 64 + r] = v;
            __nv_bfloat16 hi = __float2bfloat16_rn(v);
            __nv_bfloat16 lo = __float2bfloat16_rn(v - __bfloat162float(hi));
            g_Abf[node * 384 + r]        = hi;
            g_Abf[node * 384 + 128 + r]  = lo;
            g_Abf[node * 384 + 256 + r]  = hi;
            g_Bbf[node * 384 + 64 + r]       = hi;
            g_Bbf[node * 384 + 128 + 64 + r] = hi;
            g_Bbf[node * 384 + 256 + 64 + r] = lo;
        } else {
            float av = -v;
            g_Af[node * 128 + 64 + r] = av;
            g_Bf[node * 128 + r]      = v;
            __nv_bfloat16 ahi = __float2bfloat16_rn(av);
            __nv_bfloat16 alo = __float2bfloat16_rn(av - __bfloat162float(ahi));
            g_Abf[node * 384 + 64 + r]       = ahi;
            g_Abf[node * 384 + 128 + 64 + r] = alo;
            g_Abf[node * 384 + 256 + 64 + r] = ahi;
            __nv_bfloat16 bhi = __float2bfloat16_rn(v);
            __nv_bfloat16 blo = __float2bfloat16_rn(v - __bfloat162float(bhi));
            g_Bbf[node * 384 + r]       = bhi;
            g_Bbf[node * 384 + 128 + r] = bhi;
            g_Bbf[node * 384 + 256 + r] = blo;
        }
    }
}

// ---------------------------------------------------------------------------
// Fused kernel: identical to R8 except the cp.async issue point — chunk g+1
// is issued BEFORE chunk g's MMAs, so the wait at g+1 has a full chunk of
// compute overlap (true 2-stage pipeline).
// ---------------------------------------------------------------------------
#define OFF_A    0            // 6 chunks x 8KB = 48KB
#define OFF_B0   49152        // 32KB
#define OFF_B1   81920        // 32KB
#define OFF_CS   114688       // 64 * 256 * 4 = 65536
#define OFF_CJ   180224       // 64 * 256 * 2 = 32768
#define OFF_THR  212992
#define OFF_CNT  213248
#define SMEM_FUSED 213504

__global__ void __launch_bounds__(512) fused_kernel(
    const float* __restrict__ noise, float* __restrict__ out)
{
    extern __shared__ char smem[];
    const uint32_t sbase = smem_u32(smem);
    float*    cs  = (float*)(smem + OFF_CS);
    uint16_t* cj  = (uint16_t*)(smem + OFF_CJ);
    float*    thr = (float*)(smem + OFF_THR);
    int*      cnt = (int*)(smem + OFF_CNT);

    const int tid = threadIdx.x;
    const int lane = tid & 31;
    const int warp = tid >> 5;
    const int warpN = warp & 7;
    const int warpM = warp >> 3;
    const int rowBase = blockIdx.x * ROWS_PER_CTA;

    // zero output slab
    {
        float4* o4 = (float4*)(out + (size_t)rowBase * N_NODES);
        const float4 z = make_float4(0.f, 0.f, 0.f, 0.f);
        for (int i = tid; i < ROWS_PER_CTA * N_NODES / 4; i += 512) o4[i] = z;
    }
    if (tid < 64) { thr[tid] = -1.0f; cnt[tid] = 0; }

    // load A strip: 64 rows x 768B, 6 chunks of 8KB, SW128
    {
        const char* gA = (const char*)g_Abf;
        for (int idx = tid; idx < 3072; idx += 512) {
            int row = idx / 48, rem = idx % 48;
            int c = rem >> 3, q = rem & 7;
            uint4 v = *(const uint4*)(gA + (size_t)(rowBase + row) * 768 + c * 128 + q * 16);
            *(uint4*)(smem + OFF_A + c * 8192 + sw128(row * 128 + q * 16)) = v;
        }
    }

    const int laneRow = lane & 15;
    const int laneK = lane >> 4;
    const int rowB = tid >> 3;
    const int qB = tid & 7;
    uint32_t stB[4];
#pragma unroll
    for (int r = 0; r < 4; r++)
        stB[r] = sw128((rowB + r * 64) * 128 + qB * 16);

    const char* gB = (const char*)g_Bbf;
    const int lrBase = warpM * 32 + (lane >> 2);

    auto issueB = [&](int g) {
        const uint32_t dstBase = sbase + ((g & 1) ? OFF_B1 : OFF_B0);
        const int tt = g / 6, cc = g - tt * 6;
        const char* src = gB + (size_t)(tt * 256 + rowB) * 768 + cc * 128 + qB * 16;
#pragma unroll
        for (int r = 0; r < 4; r++)
            cp_async16(dstBase + stB[r], src + (size_t)r * 64 * 768);
        cp_commit();
    };

    issueB(0);

    for (int t = 0; t < 32; t++) {
        const int colBase = t * 256;

        float acc[2][4][4];
#pragma unroll
        for (int mi = 0; mi < 2; mi++)
#pragma unroll
            for (int n8 = 0; n8 < 4; n8++)
#pragma unroll
                for (int q = 0; q < 4; q++) acc[mi][n8][q] = 0.0f;

        for (int c = 0; c < 6; c++) {
            const int g = t * 6 + c;
            CP_WAIT(0);            // chunk g complete (issued one iteration ago)
            __syncthreads();       // all warps done reading buf^1 (chunk g-1)
            if (g < 191) issueB(g + 1);   // prefetch OVERLAPS chunk g's MMAs

            const uint32_t aBuf = sbase + OFF_A + c * 8192;
            const uint32_t bBuf = sbase + ((g & 1) ? OFF_B1 : OFF_B0);
#pragma unroll
            for (int ks = 0; ks < 4; ks++) {
                uint32_t afr[2][4];
#pragma unroll
                for (int mi = 0; mi < 2; mi++)
                    ldmatrix_x4(afr[mi][0], afr[mi][1], afr[mi][2], afr[mi][3],
                                aBuf + sw128((warpM * 32 + mi * 16 + laneRow) * 128 + ks * 32 + laneK * 16));
#pragma unroll
                for (int nq = 0; nq < 2; nq++) {
                    uint32_t r0, r1, r2, r3;
                    ldmatrix_x4(r0, r1, r2, r3,
                                bBuf + sw128((warpN * 32 + nq * 16 + laneRow) * 128 + ks * 32 + laneK * 16));
#pragma unroll
                    for (int mi = 0; mi < 2; mi++) {
                        mma_bf16(acc[mi][nq * 2],     afr[mi], r0, r2);
                        mma_bf16(acc[mi][nq * 2 + 1], afr[mi], r1, r3);
                    }
                }
            }
        }

        // ---- append: adj-only, two phases (R8 semantics, unchanged) ----
#pragma unroll 1
        for (int ph = 0; ph < 2; ph++) {
            if ((warpN >> 2) == ph) {
#pragma unroll
                for (int mi = 0; mi < 2; mi++) {
                    const int lr = lrBase + mi * 16;
                    const float th0 = thr[lr];
                    const float th1 = thr[lr + 8];
#pragma unroll
                    for (int n8 = 0; n8 < 4; n8++) {
                        const int col = colBase + warpN * 32 + n8 * 8 + (lane & 3) * 2;
                        float s0 = fmaxf(acc[mi][n8][0], 0.f);
                        float s1 = fmaxf(acc[mi][n8][1], 0.f);
                        float s2 = fmaxf(acc[mi][n8][2], 0.f);
                        float s3 = fmaxf(acc[mi][n8][3], 0.f);
                        if (s0 > th0) {
                            int p = atomicAdd(&cnt[lr], 1);
                            if (p < CAP) { cs[lr * CAP + p] = s0; cj[lr * CAP + p] = (uint16_t)col; }
                        }
                        if (s1 > th0) {
                            int p = atomicAdd(&cnt[lr], 1);
                            if (p < CAP) { cs[lr * CAP + p] = s1; cj[lr * CAP + p] = (uint16_t)(col + 1); }
                        }
                        if (s2 > th1) {
                            int p = atomicAdd(&cnt[lr + 8], 1);
                            if (p < CAP) { cs[(lr + 8) * CAP + p] = s2; cj[(lr + 8) * CAP + p] = (uint16_t)col; }
                        }
                        if (s3 > th1) {
                            int p = atomicAdd(&cnt[lr + 8], 1);
                            if (p < CAP) { cs[(lr + 8) * CAP + p] = s3; cj[(lr + 8) * CAP + p] = (uint16_t)(col + 1); }
                        }
                    }
                }
            }
            __syncthreads();

            // compaction: warp w owns rows w*4 .. w*4+3
#pragma unroll 1
            for (int rr = 0; rr < 4; rr++) {
                const int r = warp * 4 + rr;
                int n = cnt[r];
                if (n > COMPACT_HI) {
                    if (n > CAP) n = CAP;
                    unsigned sbits[8];
#pragma unroll
                    for (int q = 0; q < 8; q++) {
                        int i = lane + q * 32;
                        sbits[q] = (i < n) ? __float_as_uint(cs[r * CAP + i]) : 0u;
                    }
                    unsigned lo = 0, hi = 0x7f800000u, T = 0;
                    for (int it = 0; it < 32; it++) {
                        unsigned mid = lo + ((hi - lo) >> 1);
                        int c = 0;
#pragma unroll
                        for (int q = 0; q < 8; q++)
                            c += __popc(__ballot_sync(0xffffffffu, sbits[q] > mid));
                        if (c > 96) lo = mid + 1;
                        else if (c < 48) { if (mid == 0) { T = 0; break; } hi = mid - 1; }
                        else { T = mid; break; }
                        if (lo > hi) { T = hi; break; }
                    }
                    const float fT = fmaxf(__uint_as_float(T) - 0.01f, 1e-30f);
                    int base = 0;
#pragma unroll
                    for (int q = 0; q < 8; q++) {
                        int i = lane + q * 32;
                        bool keep = (i < n) && (__uint_as_float(sbits[q]) > fT);
                        unsigned m = __ballot_sync(0xffffffffu, keep);
                        float v; uint16_t jv;
                        if (keep) { v = cs[r * CAP + i]; jv = cj[r * CAP + i]; }
                        int pos = base + __popc(m & ((1u << lane) - 1u));
                        if (keep) { cs[r * CAP + pos] = v; cj[r * CAP + pos] = jv; }
                        base += __popc(m);
                    }
                    if (lane == 0) { cnt[r] = base; thr[r] = fT; }
                }
                __syncwarp();
            }
            __syncthreads();
        }
    }

    // ------ tail: exact rescore + exact top-32 (unchanged from R8) ------
    {
        float4* saf4 = (float4*)(smem + OFF_B0);
        for (int idx = tid; idx < 64 * 32; idx += 512) {
            int row = idx >> 5, k4 = idx & 31;
            saf4[idx] = *(const float4*)(g_Af + (size_t)(rowBase + row) * 128 + k4 * 4);
        }
    }
    __syncthreads();

    const float4* saf = (const float4*)(smem + OFF_B0);
    int* win = (int*)(smem + OFF_A) + warp * 64;

#pragma unroll 1
    for (int rr = 0; rr < 4; rr++) {
        const int r = warp * 4 + rr;
        const int rowG = rowBase + r;
        int n = cnt[r];
        if (n > CAP) n = CAP;

        for (int i = lane; i < n; i += 32) {
            const int j = (int)cj[r * CAP + i];
            float d = 0.f;
#pragma unroll
            for (int k4 = 0; k4 < 32; k4++) {
                float4 a = saf[r * 32 + k4];
                float4 b = *(const float4*)(g_Bf + (size_t)j * 128 + k4 * 4);
                d = fmaf(a.x, b.x, fmaf(a.y, b.y, fmaf(a.z, b.z, fmaf(a.w, b.w, d))));
            }
            float adjv = fmaxf(d, 0.f);
            float sc = __fadd_rn(adjv, __fmul_rn(0.01f, __ldg(noise + (size_t)rowG * N_NODES + j)));
            cs[r * CAP + i] = sc;
        }
        __syncwarp();

        unsigned sbits[8];
#pragma unroll
        for (int q = 0; q < 8; q++) {
            int i = lane + q * 32;
            sbits[q] = (i < n) ? __float_as_uint(cs[r * CAP + i]) : 0u;
        }
        unsigned lo = 0, hi = 0x7f800000u, T = 0;
        for (int it = 0; it < 32; it++) {
            unsigned mid = lo + ((hi - lo) >> 1);
            int c = 0;
#pragma unroll
            for (int q = 0; q < 8; q++)
                c += __popc(__ballot_sync(0xffffffffu, sbits[q] > mid));
            if (c > 48) lo = mid + 1;
            else if (c < 32) { if (mid == 0) { T = 0; break; } hi = mid - 1; }
            else { T = mid; break; }
            if (lo > hi) { T = hi; break; }
        }

        int wn = 0;
#pragma unroll
        for (int q = 0; q < 8; q++) {
            int i = lane + q * 32;
            bool keep = (i < n) && (sbits[q] > T);
            unsigned m = __ballot_sync(0xffffffffu, keep);
            int pos = wn + __popc(m & ((1u << lane) - 1u));
            if (keep && pos < 64) win[pos] = i;
            wn += __popc(m);
        }
        if (wn > 64) wn = 64;
        __syncwarp();

        while (wn > KSEL) {
            unsigned long long bk = ~0ull; int bp = -1;
            for (int p = lane; p < wn; p += 32) {
                int i = win[p];
                unsigned long long key =
                    ((unsigned long long)__float_as_uint(cs[r * CAP + i]) << 32)
                  | (unsigned)(0xFFFFu - cj[r * CAP + i]);
                if (key < bk) { bk = key; bp = p; }
            }
#pragma unroll
            for (int off = 16; off > 0; off >>= 1) {
                unsigned long long ok = __shfl_down_sync(0xffffffffu, bk, off);
                int op = __shfl_down_sync(0xffffffffu, bp, off);
                if (ok < bk) { bk = ok; bp = op; }
            }
            bp = __shfl_sync(0xffffffffu, bp, 0);
            if (lane == 0) win[bp] = win[wn - 1];
            __syncwarp();
            wn--;
        }

        if (lane < wn) {
            const int j = (int)cj[r * CAP + win[lane]];
            float d = 0.f;
#pragma unroll
            for (int k4 = 0; k4 < 32; k4++) {
                float4 a = saf[r * 32 + k4];
                float4 b = *(const float4*)(g_Bf + (size_t)j * 128 + k4 * 4);
                d = fmaf(a.x, b.x, fmaf(a.y, b.y, fmaf(a.z, b.z, fmaf(a.w, b.w, d))));
            }
            out[(size_t)rowG * N_NODES + j] = fmaxf(d, 0.f);
        }
        __syncwarp();
    }
}

// ---------------------------------------------------------------------------
extern "C" void kernel_launch(void* const* d_in, const int* in_sizes, int n_in,
                              void* d_out, int out_size)
{
    const float* emb   = (const float*)d_in[0];
    const float* noise = (const float*)d_in[1];
    const float* W1    = (const float*)d_in[2];
    const float* b1    = (const float*)d_in[3];
    const float* W2    = (const float*)d_in[4];
    const float* b2    = (const float*)d_in[5];
    float* out = (float*)d_out;

    cudaFuncSetAttribute(fused_kernel, cudaFuncAttributeMaxDynamicSharedMemorySize, SMEM_FUSED);

    prep_kernel<<<N_NODES / 16, 128>>>(emb, W1, b1, W2, b2);
    fused_kernel<<<N_NODES / ROWS_PER_CTA, 512, SMEM_FUSED>>>(noise, out);
}

// round 10
// speedup vs baseline: 1.7619x; 1.3531x over previous
#include <cuda_runtime.h>
#include <cuda_bf16.h>
#include <math.h>
#include <stdint.h>

#define N_NODES 8192
#define KSEL 32
#define ROWS_PER_CTA 64
#define CAP 256
#define COMPACT_HI 128

__device__ float g_Af[N_NODES * 128];                 // [v1 | -v2] fp32
__device__ float g_Bf[N_NODES * 128];                 // [v2 |  v1] fp32
__device__ __nv_bfloat16 g_Abf[N_NODES * 128];        // hi(A) only
__device__ __nv_bfloat16 g_Bbf[N_NODES * 128];        // hi(B) only

__device__ __forceinline__ uint32_t smem_u32(const void* p) {
    uint32_t a;
    asm("{ .reg .u64 t; cvta.to.shared.u64 t, %1; cvt.u32.u64 %0, t; }" : "=r"(a) : "l"(p));
    return a;
}
__device__ __forceinline__ uint32_t sw128(uint32_t byte) {
    return byte ^ ((byte >> 3) & 0x70);
}
__device__ __forceinline__ void ldmatrix_x4(uint32_t& r0, uint32_t& r1,
                                            uint32_t& r2, uint32_t& r3, uint32_t addr) {
    asm volatile("ldmatrix.sync.aligned.m8n8.x4.shared.b16 {%0,%1,%2,%3}, [%4];"
                 : "=r"(r0), "=r"(r1), "=r"(r2), "=r"(r3) : "r"(addr));
}
__device__ __forceinline__ void mma_bf16(float* c, const uint32_t* a, uint32_t b0, uint32_t b1) {
    asm volatile("mma.sync.aligned.m16n8k16.row.col.f32.bf16.bf16.f32 "
                 "{%0,%1,%2,%3}, {%4,%5,%6,%7}, {%8,%9}, {%0,%1,%2,%3};"
                 : "+f"(c[0]), "+f"(c[1]), "+f"(c[2]), "+f"(c[3])
                 : "r"(a[0]), "r"(a[1]), "r"(a[2]), "r"(a[3]), "r"(b0), "r"(b1));
}
__device__ __forceinline__ void cp_async16(uint32_t dst, const void* src) {
    asm volatile("cp.async.cg.shared.global [%0], [%1], 16;" :: "r"(dst), "l"(src) : "memory");
}
__device__ __forceinline__ void cp_commit() {
    asm volatile("cp.async.commit_group;" ::: "memory");
}
#define CP_WAIT(N) asm volatile("cp.async.wait_group %0;" :: "n"(N) : "memory")

// ---------------------------------------------------------------------------
// Kernel 1: prep — hi-only bf16 pack (K=128)
// ---------------------------------------------------------------------------
__global__ void __launch_bounds__(128) prep_kernel(
    const float* __restrict__ emb,
    const float* __restrict__ W1, const float* __restrict__ b1,
    const float* __restrict__ W2, const float* __restrict__ b2)
{
    __shared__ float sW[2][64][65];
    __shared__ float sb[2][64];
    __shared__ float semb[16][64];

    const int tid = threadIdx.x;
    for (int i = tid; i < 64 * 64; i += 128) {
        int r = i >> 6, k = i & 63;
        sW[0][r][k] = W1[i];
        sW[1][r][k] = W2[i];
    }
    if (tid < 64) { sb[0][tid] = b1[tid]; sb[1][tid] = b2[tid]; }

    const int nodeBase = blockIdx.x * 16;
    for (int i = tid; i < 16 * 64; i += 128)
        semb[i >> 6][i & 63] = emb[(size_t)(nodeBase + (i >> 6)) * 64 + (i & 63)];
    __syncthreads();

    const int h = tid >> 6;
    const int r = tid & 63;
    for (int n = 0; n < 16; n++) {
        float acc = sb[h][r];
#pragma unroll
        for (int k = 0; k < 64; k++)
            acc = fmaf(semb[n][k], sW[h][r][k], acc);
        float v = 0.5f * acc * (1.0f + erff(acc * 0.70710678118654752f));
        const int node = nodeBase + n;

        if (h == 0) {
            g_Af[node * 128 + r]      = v;
            g_Bf[node * 128 + 64 + r] = v;
            __nv_bfloat16 hi = __float2bfloat16_rn(v);
            g_Abf[node * 128 + r]      = hi;
            g_Bbf[node * 128 + 64 + r] = hi;
        } else {
            float av = -v;
            g_Af[node * 128 + 64 + r] = av;
            g_Bf[node * 128 + r]      = v;
            g_Abf[node * 128 + 64 + r] = __float2bfloat16_rn(av);
            g_Bbf[node * 128 + r]      = __float2bfloat16_rn(v);
        }
    }
}

// ---------------------------------------------------------------------------
// Fused kernel: K=128 (2 chunks/tile), otherwise R9 structure
// ---------------------------------------------------------------------------
#define OFF_A    0            // 2 chunks x 8KB = 16KB
#define OFF_B0   16384        // 32KB
#define OFF_B1   49152        // 32KB
#define OFF_CS   81920        // 64 * 256 * 4 = 65536
#define OFF_CJ   147456       // 64 * 256 * 2 = 32768
#define OFF_THR  180224
#define OFF_CNT  180480
#define SMEM_FUSED 180736

__global__ void __launch_bounds__(512) fused_kernel(
    const float* __restrict__ noise, float* __restrict__ out)
{
    extern __shared__ char smem[];
    const uint32_t sbase = smem_u32(smem);
    float*    cs  = (float*)(smem + OFF_CS);
    uint16_t* cj  = (uint16_t*)(smem + OFF_CJ);
    float*    thr = (float*)(smem + OFF_THR);
    int*      cnt = (int*)(smem + OFF_CNT);

    const int tid = threadIdx.x;
    const int lane = tid & 31;
    const int warp = tid >> 5;
    const int warpN = warp & 7;
    const int warpM = warp >> 3;
    const int rowBase = blockIdx.x * ROWS_PER_CTA;

    // zero output slab
    {
        float4* o4 = (float4*)(out + (size_t)rowBase * N_NODES);
        const float4 z = make_float4(0.f, 0.f, 0.f, 0.f);
        for (int i = tid; i < ROWS_PER_CTA * N_NODES / 4; i += 512) o4[i] = z;
    }
    if (tid < 64) { thr[tid] = -1.0f; cnt[tid] = 0; }

    // load A strip: 64 rows x 256B, 2 chunks of 8KB, SW128
    {
        const char* gA = (const char*)g_Abf;
        for (int idx = tid; idx < 1024; idx += 512) {
            int row = idx >> 4, rem = idx & 15;
            int c = rem >> 3, q = rem & 7;
            uint4 v = *(const uint4*)(gA + (size_t)(rowBase + row) * 256 + c * 128 + q * 16);
            *(uint4*)(smem + OFF_A + c * 8192 + sw128(row * 128 + q * 16)) = v;
        }
    }

    const int laneRow = lane & 15;
    const int laneK = lane >> 4;
    const int rowB = tid >> 3;
    const int qB = tid & 7;
    uint32_t stB[4];
#pragma unroll
    for (int r = 0; r < 4; r++)
        stB[r] = sw128((rowB + r * 64) * 128 + qB * 16);

    const char* gB = (const char*)g_Bbf;
    const int lrBase = warpM * 32 + (lane >> 2);

    auto issueB = [&](int g) {
        const uint32_t dstBase = sbase + ((g & 1) ? OFF_B1 : OFF_B0);
        const int tt = g >> 1, cc = g & 1;
        const char* src = gB + (size_t)(tt * 256 + rowB) * 256 + cc * 128 + qB * 16;
#pragma unroll
        for (int r = 0; r < 4; r++)
            cp_async16(dstBase + stB[r], src + (size_t)r * 64 * 256);
        cp_commit();
    };

    issueB(0);

    for (int t = 0; t < 32; t++) {
        const int colBase = t * 256;

        float acc[2][4][4];
#pragma unroll
        for (int mi = 0; mi < 2; mi++)
#pragma unroll
            for (int n8 = 0; n8 < 4; n8++)
#pragma unroll
                for (int q = 0; q < 4; q++) acc[mi][n8][q] = 0.0f;

#pragma unroll
        for (int c = 0; c < 2; c++) {
            const int g = t * 2 + c;
            CP_WAIT(0);            // chunk g complete
            __syncthreads();       // all warps done reading buf^1
            if (g < 63) issueB(g + 1);   // prefetch overlaps chunk g's MMAs

            const uint32_t aBuf = sbase + OFF_A + c * 8192;
            const uint32_t bBuf = sbase + ((g & 1) ? OFF_B1 : OFF_B0);
#pragma unroll
            for (int ks = 0; ks < 4; ks++) {
                uint32_t afr[2][4];
#pragma unroll
                for (int mi = 0; mi < 2; mi++)
                    ldmatrix_x4(afr[mi][0], afr[mi][1], afr[mi][2], afr[mi][3],
                                aBuf + sw128((warpM * 32 + mi * 16 + laneRow) * 128 + ks * 32 + laneK * 16));
#pragma unroll
                for (int nq = 0; nq < 2; nq++) {
                    uint32_t r0, r1, r2, r3;
                    ldmatrix_x4(r0, r1, r2, r3,
                                bBuf + sw128((warpN * 32 + nq * 16 + laneRow) * 128 + ks * 32 + laneK * 16));
#pragma unroll
                    for (int mi = 0; mi < 2; mi++) {
                        mma_bf16(acc[mi][nq * 2],     afr[mi], r0, r2);
                        mma_bf16(acc[mi][nq * 2 + 1], afr[mi], r1, r3);
                    }
                }
            }
        }

        // ---- append: approx-adj filter, two phases ----
#pragma unroll 1
        for (int ph = 0; ph < 2; ph++) {
            if ((warpN >> 2) == ph) {
#pragma unroll
                for (int mi = 0; mi < 2; mi++) {
                    const int lr = lrBase + mi * 16;
                    const float th0 = thr[lr];
                    const float th1 = thr[lr + 8];
#pragma unroll
                    for (int n8 = 0; n8 < 4; n8++) {
                        const int col = colBase + warpN * 32 + n8 * 8 + (lane & 3) * 2;
                        float s0 = fmaxf(acc[mi][n8][0], 0.f);
                        float s1 = fmaxf(acc[mi][n8][1], 0.f);
                        float s2 = fmaxf(acc[mi][n8][2], 0.f);
                        float s3 = fmaxf(acc[mi][n8][3], 0.f);
                        if (s0 > th0) {
                            int p = atomicAdd(&cnt[lr], 1);
                            if (p < CAP) { cs[lr * CAP + p] = s0; cj[lr * CAP + p] = (uint16_t)col; }
                        }
                        if (s1 > th0) {
                            int p = atomicAdd(&cnt[lr], 1);
                            if (p < CAP) { cs[lr * CAP + p] = s1; cj[lr * CAP + p] = (uint16_t)(col + 1); }
                        }
                        if (s2 > th1) {
                            int p = atomicAdd(&cnt[lr + 8], 1);
                            if (p < CAP) { cs[(lr + 8) * CAP + p] = s2; cj[(lr + 8) * CAP + p] = (uint16_t)col; }
                        }
                        if (s3 > th1) {
                            int p = atomicAdd(&cnt[lr + 8], 1);
                            if (p < CAP) { cs[(lr + 8) * CAP + p] = s3; cj[(lr + 8) * CAP + p] = (uint16_t)(col + 1); }
                        }
                    }
                }
            }
            __syncthreads();

            // compaction: warp w owns rows w*4 .. w*4+3
#pragma unroll 1
            for (int rr = 0; rr < 4; rr++) {
                const int r = warp * 4 + rr;
                int n = cnt[r];
                if (n > COMPACT_HI) {
                    if (n > CAP) n = CAP;
                    unsigned sbits[8];
#pragma unroll
                    for (int q = 0; q < 8; q++) {
                        int i = lane + q * 32;
                        sbits[q] = (i < n) ? __float_as_uint(cs[r * CAP + i]) : 0u;
                    }
                    unsigned lo = 0, hi = 0x7f800000u, T = 0;
                    for (int it = 0; it < 32; it++) {
                        unsigned mid = lo + ((hi - lo) >> 1);
                        int c = 0;
#pragma unroll
                        for (int q = 0; q < 8; q++)
                            c += __popc(__ballot_sync(0xffffffffu, sbits[q] > mid));
                        if (c > 96) lo = mid + 1;
                        else if (c < 48) { if (mid == 0) { T = 0; break; } hi = mid - 1; }
                        else { T = mid; break; }
                        if (lo > hi) { T = hi; break; }
                    }
                    // margin = 0.01 (noise) + 0.025 (bf16 hi-only error bound);
                    // zero-clamp keeps relu zeros out (R6 lesson)
                    const float fT = fmaxf(__uint_as_float(T) - 0.035f, 1e-30f);
                    int base = 0;
#pragma unroll
                    for (int q = 0; q < 8; q++) {
                        int i = lane + q * 32;
                        bool keep = (i < n) && (__uint_as_float(sbits[q]) > fT);
                        unsigned m = __ballot_sync(0xffffffffu, keep);
                        float v; uint16_t jv;
                        if (keep) { v = cs[r * CAP + i]; jv = cj[r * CAP + i]; }
                        int pos = base + __popc(m & ((1u << lane) - 1u));
                        if (keep) { cs[r * CAP + pos] = v; cj[r * CAP + pos] = jv; }
                        base += __popc(m);
                    }
                    if (lane == 0) { cnt[r] = base; thr[r] = fT; }
                }
                __syncwarp();
            }
            __syncthreads();
        }
    }

    // ------ tail: exact fp32 rescore + exact top-32 per row ------
    {
        float4* saf4 = (float4*)(smem + OFF_B0);   // 64 rows x 128 fp32 = 32KB
        for (int idx = tid; idx < 64 * 32; idx += 512) {
            int row = idx >> 5, k4 = idx & 31;
            saf4[idx] = *(const float4*)(g_Af + (size_t)(rowBase + row) * 128 + k4 * 4);
        }
    }
    __syncthreads();

    const float4* saf = (const float4*)(smem + OFF_B0);
    int* win = (int*)(smem + OFF_A) + warp * 64;

#pragma unroll 1
    for (int rr = 0; rr < 4; rr++) {
        const int r = warp * 4 + rr;
        const int rowG = rowBase + r;
        int n = cnt[r];
        if (n > CAP) n = CAP;

        for (int i = lane; i < n; i += 32) {
            const int j = (int)cj[r * CAP + i];
            float d = 0.f;
#pragma unroll
            for (int k4 = 0; k4 < 32; k4++) {
                float4 a = saf[r * 32 + k4];
                float4 b = *(const float4*)(g_Bf + (size_t)j * 128 + k4 * 4);
                d = fmaf(a.x, b.x, fmaf(a.y, b.y, fmaf(a.z, b.z, fmaf(a.w, b.w, d))));
            }
            float adjv = fmaxf(d, 0.f);
            float sc = __fadd_rn(adjv, __fmul_rn(0.01f, __ldg(noise + (size_t)rowG * N_NODES + j)));
            cs[r * CAP + i] = sc;
        }
        __syncwarp();

        unsigned sbits[8];
#pragma unroll
        for (int q = 0; q < 8; q++) {
            int i = lane + q * 32;
            sbits[q] = (i < n) ? __float_as_uint(cs[r * CAP + i]) : 0u;
        }
        unsigned lo = 0, hi = 0x7f800000u, T = 0;
        for (int it = 0; it < 32; it++) {
            unsigned mid = lo + ((hi - lo) >> 1);
            int c = 0;
#pragma unroll
            for (int q = 0; q < 8; q++)
                c += __popc(__ballot_sync(0xffffffffu, sbits[q] > mid));
            if (c > 48) lo = mid + 1;
            else if (c < 32) { if (mid == 0) { T = 0; break; } hi = mid - 1; }
            else { T = mid; break; }
            if (lo > hi) { T = hi; break; }
        }

        int wn = 0;
#pragma unroll
        for (int q = 0; q < 8; q++) {
            int i = lane + q * 32;
            bool keep = (i < n) && (sbits[q] > T);
            unsigned m = __ballot_sync(0xffffffffu, keep);
            int pos = wn + __popc(m & ((1u << lane) - 1u));
            if (keep && pos < 64) win[pos] = i;
            wn += __popc(m);
        }
        if (wn > 64) wn = 64;
        __syncwarp();

        while (wn > KSEL) {
            unsigned long long bk = ~0ull; int bp = -1;
            for (int p = lane; p < wn; p += 32) {
                int i = win[p];
                unsigned long long key =
                    ((unsigned long long)__float_as_uint(cs[r * CAP + i]) << 32)
                  | (unsigned)(0xFFFFu - cj[r * CAP + i]);
                if (key < bk) { bk = key; bp = p; }
            }
#pragma unroll
            for (int off = 16; off > 0; off >>= 1) {
                unsigned long long ok = __shfl_down_sync(0xffffffffu, bk, off);
                int op = __shfl_down_sync(0xffffffffu, bp, off);
                if (ok < bk) { bk = ok; bp = op; }
            }
            bp = __shfl_sync(0xffffffffu, bp, 0);
            if (lane == 0) win[bp] = win[wn - 1];
            __syncwarp();
            wn--;
        }

        if (lane < wn) {
            const int j = (int)cj[r * CAP + win[lane]];
            float d = 0.f;
#pragma unroll
            for (int k4 = 0; k4 < 32; k4++) {
                float4 a = saf[r * 32 + k4];
                float4 b = *(const float4*)(g_Bf + (size_t)j * 128 + k4 * 4);
                d = fmaf(a.x, b.x, fmaf(a.y, b.y, fmaf(a.z, b.z, fmaf(a.w, b.w, d))));
            }
            out[(size_t)rowG * N_NODES + j] = fmaxf(d, 0.f);
        }
        __syncwarp();
    }
}

// ---------------------------------------------------------------------------
extern "C" void kernel_launch(void* const* d_in, const int* in_sizes, int n_in,
                              void* d_out, int out_size)
{
    const float* emb   = (const float*)d_in[0];
    const float* noise = (const float*)d_in[1];
    const float* W1    = (const float*)d_in[2];
    const float* b1    = (const float*)d_in[3];
    const float* W2    = (const float*)d_in[4];
    const float* b2    = (const float*)d_in[5];
    float* out = (float*)d_out;

    cudaFuncSetAttribute(fused_kernel, cudaFuncAttributeMaxDynamicSharedMemorySize, SMEM_FUSED);

    prep_kernel<<<N_NODES / 16, 128>>>(emb, W1, b1, W2, b2);
    fused_kernel<<<N_NODES / ROWS_PER_CTA, 512, SMEM_FUSED>>>(noise, out);
}